// round 15
// baseline (speedup 1.0000x reference)
#include <cuda_runtime.h>
#include <cuda_bf16.h>
#include <math.h>

#define B   128
#define T   128
#define E   512
#define H   384
#define FH  1536
#define Z   128
#define ZH  256
#define NSTEP 127
#define VE  30001

typedef unsigned long long ull;

// ---------------- device scratch ----------------
__device__ float g_G0[NSTEP * FH * B];     // precomputed x@Wih0^T, layout [t][j][b]
__device__ float g_h0[2][H * B];           // ping-pong, layout [feature][batch]
__device__ float g_h1[2][H * B];
__device__ int   g_act[NSTEP];
__device__ __align__(16) int g_slot[128];
__device__ int   g_release;
// bf16 hi/lo copies (converted once per launch)
__device__ __nv_bfloat16 g_Wh[FH * E];
__device__ __nv_bfloat16 g_Wl[FH * E];
__device__ __nv_bfloat16 g_Eh[VE * E];
__device__ __nv_bfloat16 g_El[VE * E];

// ---------------- helpers ----------------
__device__ __forceinline__ ull ffma2(ull a, ull b, ull c) {
    ull d; asm("fma.rn.f32x2 %0,%1,%2,%3;" : "=l"(d) : "l"(a), "l"(b), "l"(c)); return d;
}
__device__ __forceinline__ ull pack2(float x, float y) {
    ull r; asm("mov.b64 %0,{%1,%2};" : "=l"(r) : "f"(x), "f"(y)); return r;
}
__device__ __forceinline__ float tanhap(float x) {
    float y; asm("tanh.approx.f32 %0, %1;" : "=f"(y) : "f"(x)); return y;
}
__device__ __forceinline__ float sigap(float x) {
    return fmaf(0.5f, tanhap(0.5f * x), 0.5f);
}

// R3-proven grid barrier (DO NOT TOUCH)
__device__ __forceinline__ void gsync(int epoch) {
    __threadfence();
    __syncthreads();
    if (threadIdx.x == 0) *((volatile int*)&g_slot[blockIdx.x]) = epoch;
    if (blockIdx.x == 0 && threadIdx.x < 32) {
        const volatile int* sp = g_slot;
        int i0 = threadIdx.x * 4;
        for (;;) {
            int a = sp[i0], b = sp[i0 + 1], c = sp[i0 + 2], d = sp[i0 + 3];
            bool ok = (a - epoch) >= 0 && (b - epoch) >= 0 && (c - epoch) >= 0 && (d - epoch) >= 0;
            if (__all_sync(0xffffffffu, ok)) break;
        }
        if (threadIdx.x == 0) *((volatile int*)&g_release) = epoch;
    }
    if (threadIdx.x == 0) { while ((*((volatile int*)&g_release) - epoch) < 0) {} }
    __syncthreads();
}

// ---------------- per-step nonzero flags ----------------
__global__ void act_kernel(const int* __restrict__ seq) {
    const int t = blockIdx.x;
    __shared__ int ws[4];
    int v = seq[threadIdx.x * T + t + 1];
#pragma unroll
    for (int o = 16; o > 0; o >>= 1) v += __shfl_down_sync(0xffffffffu, v, o);
    if ((threadIdx.x & 31) == 0) ws[threadIdx.x >> 5] = v;
    __syncthreads();
    if (threadIdx.x == 0)
        g_act[t] = ((ws[0] + ws[1] + ws[2] + ws[3]) != 0);
}

// ---------------- one-shot f32 -> bf16 hi/lo conversion ----------------
__global__ void cvt_kernel(const float* __restrict__ src,
                           __nv_bfloat16* __restrict__ hi,
                           __nv_bfloat16* __restrict__ lo, int n4) {
    int i = blockIdx.x * blockDim.x + threadIdx.x;
    if (i >= n4) return;
    float4 v = __ldg((const float4*)src + i);
    float f[4] = {v.x, v.y, v.z, v.w};
    unsigned short hs[4], ls[4];
#pragma unroll
    for (int j = 0; j < 4; j++) {
        __nv_bfloat16 h = __float2bfloat16(f[j]);
        __nv_bfloat16 l = __float2bfloat16(f[j] - __bfloat162float(h));
        hs[j] = __bfloat16_as_ushort(h);
        ls[j] = __bfloat16_as_ushort(l);
    }
    uint2 hv = make_uint2((unsigned)hs[0] | ((unsigned)hs[1] << 16),
                          (unsigned)hs[2] | ((unsigned)hs[3] << 16));
    uint2 lv = make_uint2((unsigned)ls[0] | ((unsigned)ls[1] << 16),
                          (unsigned)ls[2] | ((unsigned)ls[3] << 16));
    *(uint2*)(hi + 4 * (size_t)i) = hv;
    *(uint2*)(lo + 4 * (size_t)i) = lv;
}

// =====================================================================
// HMMA pre_kernel, double-buffered: stage chunk ch+1 while computing ch.
// Per kk step: LDG round kk (ch+1) -> compute kk (ch) -> STS round kk.
// MMA core identical to R12/R13 (verified, rel_err 8e-6).
// =====================================================================
#define SWZ(o) ((o) ^ (((o) >> 3) & 0x70))
#define PM_AH 0
#define PM_AL 16384
#define PM_BH 32768
#define PM_BL 49152
#define PM_BUF 65536
#define PM_SMEM 131072

__device__ __forceinline__ unsigned smem_u32(const void* p) {
    unsigned a;
    asm("{ .reg .u64 t; cvta.to.shared.u64 t, %1; cvt.u32.u64 %0, t; }" : "=r"(a) : "l"(p));
    return a;
}
#define LDSM_X4(r, addr) \
    asm volatile("ldmatrix.sync.aligned.m8n8.x4.shared.b16 {%0,%1,%2,%3}, [%4];" \
        : "=r"((r)[0]), "=r"((r)[1]), "=r"((r)[2]), "=r"((r)[3]) : "r"(addr))
#define LDSM_X2(r, addr) \
    asm volatile("ldmatrix.sync.aligned.m8n8.x2.shared.b16 {%0,%1}, [%2];" \
        : "=r"((r)[0]), "=r"((r)[1]) : "r"(addr))
#define MMA_BF16(c, a, b) \
    asm volatile("mma.sync.aligned.m16n8k16.row.col.f32.bf16.bf16.f32 " \
        "{%0,%1,%2,%3}, {%4,%5,%6,%7}, {%8,%9}, {%0,%1,%2,%3};" \
        : "+f"((c)[0]), "+f"((c)[1]), "+f"((c)[2]), "+f"((c)[3]) \
        : "r"((a)[0]), "r"((a)[1]), "r"((a)[2]), "r"((a)[3]), "r"((b)[0]), "r"((b)[1]))

extern __shared__ char dynsmem[];

__global__ __launch_bounds__(256) void pre_mma_kernel(const int* __restrict__ seq) {
    const int t  = blockIdx.y;
    const int jb = blockIdx.x * 128;
    const int tid  = threadIdx.x;
    const int wid  = tid >> 5;
    const int lane = tid & 31;
    const int wm   = (wid & 1) * 64;
    const int wn   = (wid >> 1) * 32;
    char* sm = dynsmem;
    const unsigned smb = smem_u32(sm);

    __shared__ int s_idx[128];
    if (tid < 128) s_idx[tid] = (int)seq[tid * T + t + 1];
    __syncthreads();

    // staging geometry for this thread (4 rounds x 4 tiles)
    const int srow[4] = { (0 * 256 + tid) >> 3, (1 * 256 + tid) >> 3,
                          (2 * 256 + tid) >> 3, (3 * 256 + tid) >> 3 };
    const int sc16    = tid & 7;
    const unsigned ssw[4] = { SWZ((unsigned)(srow[0] * 128 + sc16 * 16)),
                              SWZ((unsigned)(srow[1] * 128 + sc16 * 16)),
                              SWZ((unsigned)(srow[2] * 128 + sc16 * 16)),
                              SWZ((unsigned)(srow[3] * 128 + sc16 * 16)) };

    float c[4][4][4];
#pragma unroll
    for (int mt = 0; mt < 4; mt++)
#pragma unroll
        for (int nt = 0; nt < 4; nt++)
#pragma unroll
            for (int q = 0; q < 4; q++) c[mt][nt][q] = 0.0f;

    // ---- prologue: stage chunk 0 into buffer 0
#pragma unroll
    for (int i = 0; i < 4; i++) {
        size_t aoff = (size_t)(jb + srow[i]) * E + sc16 * 8;
        size_t boff = (size_t)s_idx[srow[i]] * E + sc16 * 8;
        *(uint4*)(sm + PM_AH + ssw[i]) = __ldg((const uint4*)(g_Wh + aoff));
        *(uint4*)(sm + PM_AL + ssw[i]) = __ldg((const uint4*)(g_Wl + aoff));
        *(uint4*)(sm + PM_BH + ssw[i]) = __ldg((const uint4*)(g_Eh + boff));
        *(uint4*)(sm + PM_BL + ssw[i]) = __ldg((const uint4*)(g_El + boff));
    }
    __syncthreads();

    for (int ch = 0; ch < 8; ch++) {
        const unsigned cb = (unsigned)(ch & 1) * PM_BUF;        // compute buffer
        const unsigned nb = cb ^ PM_BUF;                        // staging buffer
        const bool more = (ch < 7);
        const int kcn = (ch + 1) * 64;                          // next chunk k-base

#pragma unroll
        for (int kk = 0; kk < 4; kk++) {
            // ---- LDG staging round kk of chunk ch+1 (latency hidden by compute)
            uint4 ra, rb0, rc, rd;
            if (more) {
                size_t aoff = (size_t)(jb + srow[kk]) * E + kcn + sc16 * 8;
                size_t boff = (size_t)s_idx[srow[kk]] * E + kcn + sc16 * 8;
                ra  = __ldg((const uint4*)(g_Wh + aoff));
                rb0 = __ldg((const uint4*)(g_Wl + aoff));
                rc  = __ldg((const uint4*)(g_Eh + boff));
                rd  = __ldg((const uint4*)(g_El + boff));
            }

            // ---- compute k16 step kk of chunk ch
            const int k0 = kk * 16;
            unsigned bh[4][2], bl[4][2];
#pragma unroll
            for (int nt = 0; nt < 4; nt++) {
                unsigned o = SWZ((unsigned)((wn + nt * 8 + (lane & 7)) * 128 +
                                            (k0 + ((lane >> 3) & 1) * 8) * 2));
                LDSM_X2(bh[nt], smb + cb + PM_BH + o);
                LDSM_X2(bl[nt], smb + cb + PM_BL + o);
            }
#pragma unroll
            for (int mt = 0; mt < 4; mt++) {
                unsigned ah[4], al[4];
                unsigned o = SWZ((unsigned)((wm + mt * 16 + (lane & 15)) * 128 +
                                            (k0 + (lane >> 4) * 8) * 2));
                LDSM_X4(ah, smb + cb + PM_AH + o);
                LDSM_X4(al, smb + cb + PM_AL + o);
#pragma unroll
                for (int nt = 0; nt < 4; nt++) {
                    MMA_BF16(c[mt][nt], ah, bh[nt]);
                    MMA_BF16(c[mt][nt], ah, bl[nt]);
                    MMA_BF16(c[mt][nt], al, bh[nt]);
                }
            }

            // ---- STS staging round kk into the other buffer
            if (more) {
                char* d = sm + nb;
                *(uint4*)(d + PM_AH + ssw[kk]) = ra;
                *(uint4*)(d + PM_AL + ssw[kk]) = rb0;
                *(uint4*)(d + PM_BH + ssw[kk]) = rc;
                *(uint4*)(d + PM_BL + ssw[kk]) = rd;
            }
        }
        __syncthreads();   // staging of ch+1 done; reads of cb done before reuse
    }

    // ---- store fragments
#pragma unroll
    for (int mt = 0; mt < 4; mt++) {
        int j = jb + wm + mt * 16 + (lane >> 2);
#pragma unroll
        for (int nt = 0; nt < 4; nt++) {
            int n = wn + nt * 8 + 2 * (lane & 3);
            float* d0 = g_G0 + ((size_t)t * FH + j) * B + n;
            *(float2*)d0 = make_float2(c[mt][nt][0], c[mt][nt][1]);
            *(float2*)(d0 + 8 * B) = make_float2(c[mt][nt][2], c[mt][nt][3]);
        }
    }
}

// ---------------- persistent recurrent kernel + VAE head (R10, unchanged) ----------------
__global__ __launch_bounds__(384, 1) void rnn_kernel(
    const float* __restrict__ Whh0, const float* __restrict__ Wih1,
    const float* __restrict__ Whh1, const float* __restrict__ eps,
    const float* __restrict__ W1,   const float* __restrict__ bias1,
    const float* __restrict__ Wmu,  const float* __restrict__ bmu,
    const float* __restrict__ Wlv,  const float* __restrict__ blv,
    float* __restrict__ out) {

    float2* sW0p = (float2*)dynsmem;
    float2* sW1p = (float2*)(dynsmem + 36864);
    float*  sRedP = (float*)(dynsmem + 36864 + 73728);

    const int tid  = threadIdx.x;
    const int lane = tid & 31;
    const int w    = tid >> 5;
    const int bx   = blockIdx.x;
    const int RG   = bx >> 1;
    const int BOFF = (bx & 1) * 64;

    for (int i = tid; i < 384 * 12; i += 384) {
        int k = i / 12, rp = i % 12;
        int g = rp / 3, fp = rp % 3;
        int j0 = g * H + RG * 6 + fp * 2;
        sW0p[i] = make_float2(Whh0[j0 * H + k], Whh0[(j0 + 1) * H + k]);
    }
    for (int i = tid; i < 768 * 12; i += 384) {
        int k = i / 12, rp = i % 12;
        int g = rp / 3, fp = rp % 3;
        int j0 = g * H + RG * 6 + fp * 2;
        float a, bv;
        if (k < 384) { a = Wih1[j0 * H + k];        bv = Wih1[(j0 + 1) * H + k]; }
        else         { a = Whh1[j0 * H + k - 384];  bv = Whh1[(j0 + 1) * H + k - 384]; }
        sW1p[i] = make_float2(a, bv);
    }
    const int e_sidx = tid & 127;
    const int e_rpo  = tid >> 7;
    const int e_ri   = e_sidx & 1;
    const int e_bl   = e_sidx >> 1;
    const int hrow   = RG * 6 + e_rpo * 2 + e_ri;
    {
        int idx = hrow * B + BOFF + e_bl;
        g_h0[0][idx] = 0.0f;
        g_h1[0][idx] = 0.0f;
    }
    float c0r = 0.0f, c1r = 0.0f;

    const int ebase = *((volatile int*)&g_release);
    int epoch = ebase;
    gsync(++epoch);

    int p = 0;
    int t;
    for (t = 0; t < NSTEP; t++) {
        if (!g_act[t]) break;
        const float* h0r = g_h0[p];
        float*       h0w = g_h0[p ^ 1];
        const float* h1r = g_h1[p];
        float*       h1w = g_h1[p ^ 1];

        float g0p[4];
#pragma unroll
        for (int g = 0; g < 4; g++)
            g0p[g] = __ldcs(g_G0 + ((size_t)t * FH + g * H + hrow) * B + BOFF + e_bl);

        {
            ull acc[12][2];
#pragma unroll
            for (int r = 0; r < 12; r++) { acc[r][0] = 0ull; acc[r][1] = 0ull; }
            const int k0 = w * 32;
            float2 buf[3][4];
#pragma unroll
            for (int gq = 0; gq < 3; gq++)
#pragma unroll
                for (int j = 0; j < 4; j++)
                    buf[gq][j] = __ldcg((const float2*)(h0r + (k0 + gq * 4 + j) * B + BOFF) + lane);
#pragma unroll
            for (int gq = 0; gq < 8; gq++) {
                const int cur = gq % 3;
                float2 cb[4];
#pragma unroll
                for (int j = 0; j < 4; j++) cb[j] = buf[cur][j];
                if (gq + 3 < 8) {
#pragma unroll
                    for (int j = 0; j < 4; j++)
                        buf[cur][j] = __ldcg((const float2*)(h0r + (k0 + (gq + 3) * 4 + j) * B + BOFF) + lane);
                }
#pragma unroll
                for (int j = 0; j < 4; j++) {
                    ull hd0 = pack2(cb[j].x, cb[j].x);
                    ull hd1 = pack2(cb[j].y, cb[j].y);
                    const ulonglong2* wb = (const ulonglong2*)(sW0p + (k0 + gq * 4 + j) * 12);
#pragma unroll
                    for (int q = 0; q < 6; q++) {
                        ulonglong2 ww = wb[q];
                        acc[2 * q][0]     = ffma2(hd0, ww.x, acc[2 * q][0]);
                        acc[2 * q][1]     = ffma2(hd1, ww.x, acc[2 * q][1]);
                        acc[2 * q + 1][0] = ffma2(hd0, ww.y, acc[2 * q + 1][0]);
                        acc[2 * q + 1][1] = ffma2(hd1, ww.y, acc[2 * q + 1][1]);
                    }
                }
            }
#pragma unroll
            for (int r = 0; r < 12; r++) {
                ulonglong2 v; v.x = acc[r][0]; v.y = acc[r][1];
                *(ulonglong2*)(sRedP + (w * 12 + r) * 128 + 4 * lane) = v;
            }
        }
        __syncthreads();
        {
            float gv[4];
#pragma unroll
            for (int g = 0; g < 4; g++) {
                float s = g0p[g];
                int base = (g * 3 + e_rpo) * 128 + e_sidx;
#pragma unroll
                for (int w2 = 0; w2 < 12; w2++) s += sRedP[w2 * 12 * 128 + base];
                gv[g] = s;
            }
            float nc = sigap(gv[1]) * c0r + sigap(gv[0]) * tanhap(gv[2]);
            c0r = nc;
            __stcg(h0w + hrow * B + BOFF + e_bl, sigap(gv[3]) * tanhap(nc));
        }
        gsync(++epoch);

        {
            ull acc[12][2];
#pragma unroll
            for (int r = 0; r < 12; r++) { acc[r][0] = 0ull; acc[r][1] = 0ull; }
            const float* src   = (w < 6) ? h0w : h1r;
            const int    fbase = (w < 6) ? w * 64 : (w - 6) * 64;
            const int    k0    = w * 64;
            float2 buf[3][4];
#pragma unroll
            for (int gq = 0; gq < 3; gq++)
#pragma unroll
                for (int j = 0; j < 4; j++)
                    buf[gq][j] = __ldcg((const float2*)(src + (fbase + gq * 4 + j) * B + BOFF) + lane);
#pragma unroll
            for (int gq = 0; gq < 16; gq++) {
                const int cur = gq % 3;
                float2 cb[4];
#pragma unroll
                for (int j = 0; j < 4; j++) cb[j] = buf[cur][j];
                if (gq + 3 < 16) {
#pragma unroll
                    for (int j = 0; j < 4; j++)
                        buf[cur][j] = __ldcg((const float2*)(src + (fbase + (gq + 3) * 4 + j) * B + BOFF) + lane);
                }
#pragma unroll
                for (int j = 0; j < 4; j++) {
                    ull hd0 = pack2(cb[j].x, cb[j].x);
                    ull hd1 = pack2(cb[j].y, cb[j].y);
                    const ulonglong2* wb = (const ulonglong2*)(sW1p + (k0 + gq * 4 + j) * 12);
#pragma unroll
                    for (int q = 0; q < 6; q++) {
                        ulonglong2 ww = wb[q];
                        acc[2 * q][0]     = ffma2(hd0, ww.x, acc[2 * q][0]);
                        acc[2 * q][1]     = ffma2(hd1, ww.x, acc[2 * q][1]);
                        acc[2 * q + 1][0] = ffma2(hd0, ww.y, acc[2 * q + 1][0]);
                        acc[2 * q + 1][1] = ffma2(hd1, ww.y, acc[2 * q + 1][1]);
                    }
                }
            }
#pragma unroll
            for (int r = 0; r < 12; r++) {
                ulonglong2 v; v.x = acc[r][0]; v.y = acc[r][1];
                *(ulonglong2*)(sRedP + (w * 12 + r) * 128 + 4 * lane) = v;
            }
        }
        __syncthreads();
        {
            float gv[4];
#pragma unroll
            for (int g = 0; g < 4; g++) {
                float s = 0.0f;
                int base = (g * 3 + e_rpo) * 128 + e_sidx;
#pragma unroll
                for (int w2 = 0; w2 < 12; w2++) s += sRedP[w2 * 12 * 128 + base];
                gv[g] = s;
            }
            float nc = sigap(gv[1]) * c1r + sigap(gv[0]) * tanhap(gv[2]);
            c1r = nc;
            __stcg(h1w + hrow * B + BOFF + e_bl, sigap(gv[3]) * tanhap(nc));
        }
        __syncthreads();
        p ^= 1;
    }

    gsync(++epoch);

    float* s_hb = sRedP;
    float* s_hv = sRedP + 512;
    const float* h1f = g_h1[p];
    const int b = bx;
    s_hb[tid] = __ldcg(h1f + tid * B + b);   // tid < 384 == H
    __syncthreads();
    if (tid < ZH) {
        float a = bias1[tid];
        const float* wr = W1 + tid * H;
#pragma unroll 4
        for (int k = 0; k < H; k++) a = fmaf(s_hb[k], __ldg(wr + k), a);
        s_hv[tid] = fmaxf(a, 0.0f);
    }
    __syncthreads();
    if (tid < Z) {
        float mu = bmu[tid], lv = blv[tid];
        const float* wmu = Wmu + tid * ZH;
        const float* wlv = Wlv + tid * ZH;
#pragma unroll 4
        for (int k = 0; k < ZH; k++) {
            float hk = s_hv[k];
            mu = fmaf(hk, __ldg(wmu + k), mu);
            lv = fmaf(hk, __ldg(wlv + k), lv);
        }
        float zz = mu + eps[b * Z + tid] * expf(0.5f * lv);
        out[b * Z + tid] = mu;
        out[B * Z + b * Z + tid] = lv;
        out[2 * B * Z + b * (H + Z) + H + tid] = zz;
    }
    out[2 * B * Z + b * (H + Z) + tid] = s_hb[tid];   // tid < 384 == H
}

// ---------------- launch ----------------
extern "C" void kernel_launch(void* const* d_in, const int* in_sizes, int n_in,
                              void* d_out, int out_size) {
    const int*   seq   = (const int*)d_in[0];
    const float* eps   = (const float*)d_in[1];
    const float* embed = (const float*)d_in[2];
    const float* Wih0  = (const float*)d_in[3];
    const float* Whh0  = (const float*)d_in[4];
    const float* Wih1  = (const float*)d_in[5];
    const float* Whh1  = (const float*)d_in[6];
    const float* W1    = (const float*)d_in[7];
    const float* b1    = (const float*)d_in[8];
    const float* Wmu   = (const float*)d_in[9];
    const float* bmu   = (const float*)d_in[10];
    const float* Wlv   = (const float*)d_in[11];
    const float* blv   = (const float*)d_in[12];
    float* out = (float*)d_out;

    static int smem_set = 0;
    const int dyn_rnn = 36864 + 73728 + 73728;   // 184320
    if (!smem_set) {
        cudaFuncSetAttribute(rnn_kernel, cudaFuncAttributeMaxDynamicSharedMemorySize, dyn_rnn);
        cudaFuncSetAttribute(pre_mma_kernel, cudaFuncAttributeMaxDynamicSharedMemorySize, PM_SMEM);
        smem_set = 1;
    }

    __nv_bfloat16 *wh, *wl, *eh, *el;
    cudaGetSymbolAddress((void**)&wh, g_Wh);
    cudaGetSymbolAddress((void**)&wl, g_Wl);
    cudaGetSymbolAddress((void**)&eh, g_Eh);
    cudaGetSymbolAddress((void**)&el, g_El);

    act_kernel<<<NSTEP, 128>>>(seq);
    cvt_kernel<<<(FH * E / 4 + 255) / 256, 256>>>(Wih0, wh, wl, FH * E / 4);
    cvt_kernel<<<(VE * E / 4 + 255) / 256, 256>>>(embed, eh, el, VE * E / 4);
    pre_mma_kernel<<<dim3(12, 127), 256, PM_SMEM>>>(seq);
    rnn_kernel<<<128, 384, dyn_rnn>>>(Whh0, Wih1, Whh1, eps, W1, b1, Wmu, bmu, Wlv, blv, out);
}

// round 16
// speedup vs baseline: 1.0149x; 1.0149x over previous
#include <cuda_runtime.h>
#include <cuda_bf16.h>
#include <math.h>

#define B   128
#define T   128
#define E   512
#define H   384
#define FH  1536
#define Z   128
#define ZH  256
#define NSTEP 127
#define VE  30001

typedef unsigned long long ull;

// ---------------- device scratch ----------------
__device__ float g_G0[NSTEP * FH * B];     // precomputed x@Wih0^T, layout [t][j][b]
__device__ float g_h0[2][H * B];           // ping-pong, layout [feature][batch]
__device__ float g_h1[2][H * B];
__device__ int   g_act[NSTEP];
__device__ __align__(16) int g_slot[128];
__device__ int   g_release;
// bf16 hi/lo copies (converted once per launch)
__device__ __nv_bfloat16 g_Wh[FH * E];
__device__ __nv_bfloat16 g_Wl[FH * E];
__device__ __nv_bfloat16 g_Eh[VE * E];
__device__ __nv_bfloat16 g_El[VE * E];

// ---------------- helpers ----------------
__device__ __forceinline__ ull ffma2(ull a, ull b, ull c) {
    ull d; asm("fma.rn.f32x2 %0,%1,%2,%3;" : "=l"(d) : "l"(a), "l"(b), "l"(c)); return d;
}
__device__ __forceinline__ ull pack2(float x, float y) {
    ull r; asm("mov.b64 %0,{%1,%2};" : "=l"(r) : "f"(x), "f"(y)); return r;
}
__device__ __forceinline__ float tanhap(float x) {
    float y; asm("tanh.approx.f32 %0, %1;" : "=f"(y) : "f"(x)); return y;
}
__device__ __forceinline__ float sigap(float x) {
    return fmaf(0.5f, tanhap(0.5f * x), 0.5f);
}

// R3-proven grid barrier (DO NOT TOUCH)
__device__ __forceinline__ void gsync(int epoch) {
    __threadfence();
    __syncthreads();
    if (threadIdx.x == 0) *((volatile int*)&g_slot[blockIdx.x]) = epoch;
    if (blockIdx.x == 0 && threadIdx.x < 32) {
        const volatile int* sp = g_slot;
        int i0 = threadIdx.x * 4;
        for (;;) {
            int a = sp[i0], b = sp[i0 + 1], c = sp[i0 + 2], d = sp[i0 + 3];
            bool ok = (a - epoch) >= 0 && (b - epoch) >= 0 && (c - epoch) >= 0 && (d - epoch) >= 0;
            if (__all_sync(0xffffffffu, ok)) break;
        }
        if (threadIdx.x == 0) *((volatile int*)&g_release) = epoch;
    }
    if (threadIdx.x == 0) { while ((*((volatile int*)&g_release) - epoch) < 0) {} }
    __syncthreads();
}

// ---------------- per-step nonzero flags ----------------
__global__ void act_kernel(const int* __restrict__ seq) {
    const int t = blockIdx.x;
    __shared__ int ws[4];
    int v = seq[threadIdx.x * T + t + 1];
#pragma unroll
    for (int o = 16; o > 0; o >>= 1) v += __shfl_down_sync(0xffffffffu, v, o);
    if ((threadIdx.x & 31) == 0) ws[threadIdx.x >> 5] = v;
    __syncthreads();
    if (threadIdx.x == 0)
        g_act[t] = ((ws[0] + ws[1] + ws[2] + ws[3]) != 0);
}

// ---------------- one-shot f32 -> bf16 hi/lo conversion ----------------
__global__ void cvt_kernel(const float* __restrict__ src,
                           __nv_bfloat16* __restrict__ hi,
                           __nv_bfloat16* __restrict__ lo, int n4) {
    int i = blockIdx.x * blockDim.x + threadIdx.x;
    if (i >= n4) return;
    float4 v = __ldg((const float4*)src + i);
    float f[4] = {v.x, v.y, v.z, v.w};
    unsigned short hs[4], ls[4];
#pragma unroll
    for (int j = 0; j < 4; j++) {
        __nv_bfloat16 h = __float2bfloat16(f[j]);
        __nv_bfloat16 l = __float2bfloat16(f[j] - __bfloat162float(h));
        hs[j] = __bfloat16_as_ushort(h);
        ls[j] = __bfloat16_as_ushort(l);
    }
    uint2 hv = make_uint2((unsigned)hs[0] | ((unsigned)hs[1] << 16),
                          (unsigned)hs[2] | ((unsigned)hs[3] << 16));
    uint2 lv = make_uint2((unsigned)ls[0] | ((unsigned)ls[1] << 16),
                          (unsigned)ls[2] | ((unsigned)ls[3] << 16));
    *(uint2*)(hi + 4 * (size_t)i) = hv;
    *(uint2*)(lo + 4 * (size_t)i) = lv;
}

// =====================================================================
// HMMA pre_kernel, double-buffered: stage chunk ch+1 while computing ch.
// Per kk step: LDG round kk (ch+1) -> compute kk (ch) -> STS round kk.
// MMA core identical to R12/R13 (verified, rel_err 8e-6).
// =====================================================================
#define SWZ(o) ((o) ^ (((o) >> 3) & 0x70))
#define PM_AH 0
#define PM_AL 16384
#define PM_BH 32768
#define PM_BL 49152
#define PM_BUF 65536
#define PM_SMEM 131072

__device__ __forceinline__ unsigned smem_u32(const void* p) {
    unsigned a;
    asm("{ .reg .u64 t; cvta.to.shared.u64 t, %1; cvt.u32.u64 %0, t; }" : "=r"(a) : "l"(p));
    return a;
}
#define LDSM_X4(r, addr) \
    asm volatile("ldmatrix.sync.aligned.m8n8.x4.shared.b16 {%0,%1,%2,%3}, [%4];" \
        : "=r"((r)[0]), "=r"((r)[1]), "=r"((r)[2]), "=r"((r)[3]) : "r"(addr))
#define LDSM_X2(r, addr) \
    asm volatile("ldmatrix.sync.aligned.m8n8.x2.shared.b16 {%0,%1}, [%2];" \
        : "=r"((r)[0]), "=r"((r)[1]) : "r"(addr))
#define MMA_BF16(c, a, b) \
    asm volatile("mma.sync.aligned.m16n8k16.row.col.f32.bf16.bf16.f32 " \
        "{%0,%1,%2,%3}, {%4,%5,%6,%7}, {%8,%9}, {%0,%1,%2,%3};" \
        : "+f"((c)[0]), "+f"((c)[1]), "+f"((c)[2]), "+f"((c)[3]) \
        : "r"((a)[0]), "r"((a)[1]), "r"((a)[2]), "r"((a)[3]), "r"((b)[0]), "r"((b)[1]))

extern __shared__ char dynsmem[];

__global__ __launch_bounds__(256) void pre_mma_kernel(const int* __restrict__ seq) {
    const int t  = blockIdx.y;
    const int jb = blockIdx.x * 128;
    const int tid  = threadIdx.x;
    const int wid  = tid >> 5;
    const int lane = tid & 31;
    const int wm   = (wid & 1) * 64;
    const int wn   = (wid >> 1) * 32;
    char* sm = dynsmem;
    const unsigned smb = smem_u32(sm);

    __shared__ int s_idx[128];
    if (tid < 128) s_idx[tid] = (int)seq[tid * T + t + 1];
    __syncthreads();

    // staging geometry for this thread (4 rounds x 4 tiles)
    const int srow[4] = { (0 * 256 + tid) >> 3, (1 * 256 + tid) >> 3,
                          (2 * 256 + tid) >> 3, (3 * 256 + tid) >> 3 };
    const int sc16    = tid & 7;
    const unsigned ssw[4] = { SWZ((unsigned)(srow[0] * 128 + sc16 * 16)),
                              SWZ((unsigned)(srow[1] * 128 + sc16 * 16)),
                              SWZ((unsigned)(srow[2] * 128 + sc16 * 16)),
                              SWZ((unsigned)(srow[3] * 128 + sc16 * 16)) };

    float c[4][4][4];
#pragma unroll
    for (int mt = 0; mt < 4; mt++)
#pragma unroll
        for (int nt = 0; nt < 4; nt++)
#pragma unroll
            for (int q = 0; q < 4; q++) c[mt][nt][q] = 0.0f;

    // ---- prologue: stage chunk 0 into buffer 0
#pragma unroll
    for (int i = 0; i < 4; i++) {
        size_t aoff = (size_t)(jb + srow[i]) * E + sc16 * 8;
        size_t boff = (size_t)s_idx[srow[i]] * E + sc16 * 8;
        *(uint4*)(sm + PM_AH + ssw[i]) = __ldg((const uint4*)(g_Wh + aoff));
        *(uint4*)(sm + PM_AL + ssw[i]) = __ldg((const uint4*)(g_Wl + aoff));
        *(uint4*)(sm + PM_BH + ssw[i]) = __ldg((const uint4*)(g_Eh + boff));
        *(uint4*)(sm + PM_BL + ssw[i]) = __ldg((const uint4*)(g_El + boff));
    }
    __syncthreads();

    for (int ch = 0; ch < 8; ch++) {
        const unsigned cb = (unsigned)(ch & 1) * PM_BUF;        // compute buffer
        const unsigned nb = cb ^ PM_BUF;                        // staging buffer
        const bool more = (ch < 7);
        const int kcn = (ch + 1) * 64;                          // next chunk k-base

#pragma unroll
        for (int kk = 0; kk < 4; kk++) {
            // ---- LDG staging round kk of chunk ch+1 (latency hidden by compute)
            uint4 ra, rb0, rc, rd;
            if (more) {
                size_t aoff = (size_t)(jb + srow[kk]) * E + kcn + sc16 * 8;
                size_t boff = (size_t)s_idx[srow[kk]] * E + kcn + sc16 * 8;
                ra  = __ldg((const uint4*)(g_Wh + aoff));
                rb0 = __ldg((const uint4*)(g_Wl + aoff));
                rc  = __ldg((const uint4*)(g_Eh + boff));
                rd  = __ldg((const uint4*)(g_El + boff));
            }

            // ---- compute k16 step kk of chunk ch
            const int k0 = kk * 16;
            unsigned bh[4][2], bl[4][2];
#pragma unroll
            for (int nt = 0; nt < 4; nt++) {
                unsigned o = SWZ((unsigned)((wn + nt * 8 + (lane & 7)) * 128 +
                                            (k0 + ((lane >> 3) & 1) * 8) * 2));
                LDSM_X2(bh[nt], smb + cb + PM_BH + o);
                LDSM_X2(bl[nt], smb + cb + PM_BL + o);
            }
#pragma unroll
            for (int mt = 0; mt < 4; mt++) {
                unsigned ah[4], al[4];
                unsigned o = SWZ((unsigned)((wm + mt * 16 + (lane & 15)) * 128 +
                                            (k0 + (lane >> 4) * 8) * 2));
                LDSM_X4(ah, smb + cb + PM_AH + o);
                LDSM_X4(al, smb + cb + PM_AL + o);
#pragma unroll
                for (int nt = 0; nt < 4; nt++) {
                    MMA_BF16(c[mt][nt], ah, bh[nt]);
                    MMA_BF16(c[mt][nt], ah, bl[nt]);
                    MMA_BF16(c[mt][nt], al, bh[nt]);
                }
            }

            // ---- STS staging round kk into the other buffer
            if (more) {
                char* d = sm + nb;
                *(uint4*)(d + PM_AH + ssw[kk]) = ra;
                *(uint4*)(d + PM_AL + ssw[kk]) = rb0;
                *(uint4*)(d + PM_BH + ssw[kk]) = rc;
                *(uint4*)(d + PM_BL + ssw[kk]) = rd;
            }
        }
        __syncthreads();   // staging of ch+1 done; reads of cb done before reuse
    }

    // ---- store fragments
#pragma unroll
    for (int mt = 0; mt < 4; mt++) {
        int j = jb + wm + mt * 16 + (lane >> 2);
#pragma unroll
        for (int nt = 0; nt < 4; nt++) {
            int n = wn + nt * 8 + 2 * (lane & 3);
            float* d0 = g_G0 + ((size_t)t * FH + j) * B + n;
            *(float2*)d0 = make_float2(c[mt][nt][0], c[mt][nt][1]);
            *(float2*)(d0 + 8 * B) = make_float2(c[mt][nt][2], c[mt][nt][3]);
        }
    }
}

// ---------------- persistent recurrent kernel + VAE head (R10, unchanged) ----------------
__global__ __launch_bounds__(384, 1) void rnn_kernel(
    const float* __restrict__ Whh0, const float* __restrict__ Wih1,
    const float* __restrict__ Whh1, const float* __restrict__ eps,
    const float* __restrict__ W1,   const float* __restrict__ bias1,
    const float* __restrict__ Wmu,  const float* __restrict__ bmu,
    const float* __restrict__ Wlv,  const float* __restrict__ blv,
    float* __restrict__ out) {

    float2* sW0p = (float2*)dynsmem;
    float2* sW1p = (float2*)(dynsmem + 36864);
    float*  sRedP = (float*)(dynsmem + 36864 + 73728);

    const int tid  = threadIdx.x;
    const int lane = tid & 31;
    const int w    = tid >> 5;
    const int bx   = blockIdx.x;
    const int RG   = bx >> 1;
    const int BOFF = (bx & 1) * 64;

    for (int i = tid; i < 384 * 12; i += 384) {
        int k = i / 12, rp = i % 12;
        int g = rp / 3, fp = rp % 3;
        int j0 = g * H + RG * 6 + fp * 2;
        sW0p[i] = make_float2(Whh0[j0 * H + k], Whh0[(j0 + 1) * H + k]);
    }
    for (int i = tid; i < 768 * 12; i += 384) {
        int k = i / 12, rp = i % 12;
        int g = rp / 3, fp = rp % 3;
        int j0 = g * H + RG * 6 + fp * 2;
        float a, bv;
        if (k < 384) { a = Wih1[j0 * H + k];        bv = Wih1[(j0 + 1) * H + k]; }
        else         { a = Whh1[j0 * H + k - 384];  bv = Whh1[(j0 + 1) * H + k - 384]; }
        sW1p[i] = make_float2(a, bv);
    }
    const int e_sidx = tid & 127;
    const int e_rpo  = tid >> 7;
    const int e_ri   = e_sidx & 1;
    const int e_bl   = e_sidx >> 1;
    const int hrow   = RG * 6 + e_rpo * 2 + e_ri;
    {
        int idx = hrow * B + BOFF + e_bl;
        g_h0[0][idx] = 0.0f;
        g_h1[0][idx] = 0.0f;
    }
    float c0r = 0.0f, c1r = 0.0f;

    const int ebase = *((volatile int*)&g_release);
    int epoch = ebase;
    gsync(++epoch);

    int p = 0;
    int t;
    for (t = 0; t < NSTEP; t++) {
        if (!g_act[t]) break;
        const float* h0r = g_h0[p];
        float*       h0w = g_h0[p ^ 1];
        const float* h1r = g_h1[p];
        float*       h1w = g_h1[p ^ 1];

        float g0p[4];
#pragma unroll
        for (int g = 0; g < 4; g++)
            g0p[g] = __ldcs(g_G0 + ((size_t)t * FH + g * H + hrow) * B + BOFF + e_bl);

        {
            ull acc[12][2];
#pragma unroll
            for (int r = 0; r < 12; r++) { acc[r][0] = 0ull; acc[r][1] = 0ull; }
            const int k0 = w * 32;
            float2 buf[3][4];
#pragma unroll
            for (int gq = 0; gq < 3; gq++)
#pragma unroll
                for (int j = 0; j < 4; j++)
                    buf[gq][j] = __ldcg((const float2*)(h0r + (k0 + gq * 4 + j) * B + BOFF) + lane);
#pragma unroll
            for (int gq = 0; gq < 8; gq++) {
                const int cur = gq % 3;
                float2 cb[4];
#pragma unroll
                for (int j = 0; j < 4; j++) cb[j] = buf[cur][j];
                if (gq + 3 < 8) {
#pragma unroll
                    for (int j = 0; j < 4; j++)
                        buf[cur][j] = __ldcg((const float2*)(h0r + (k0 + (gq + 3) * 4 + j) * B + BOFF) + lane);
                }
#pragma unroll
                for (int j = 0; j < 4; j++) {
                    ull hd0 = pack2(cb[j].x, cb[j].x);
                    ull hd1 = pack2(cb[j].y, cb[j].y);
                    const ulonglong2* wb = (const ulonglong2*)(sW0p + (k0 + gq * 4 + j) * 12);
#pragma unroll
                    for (int q = 0; q < 6; q++) {
                        ulonglong2 ww = wb[q];
                        acc[2 * q][0]     = ffma2(hd0, ww.x, acc[2 * q][0]);
                        acc[2 * q][1]     = ffma2(hd1, ww.x, acc[2 * q][1]);
                        acc[2 * q + 1][0] = ffma2(hd0, ww.y, acc[2 * q + 1][0]);
                        acc[2 * q + 1][1] = ffma2(hd1, ww.y, acc[2 * q + 1][1]);
                    }
                }
            }
#pragma unroll
            for (int r = 0; r < 12; r++) {
                ulonglong2 v; v.x = acc[r][0]; v.y = acc[r][1];
                *(ulonglong2*)(sRedP + (w * 12 + r) * 128 + 4 * lane) = v;
            }
        }
        __syncthreads();
        {
            float gv[4];
#pragma unroll
            for (int g = 0; g < 4; g++) {
                float s = g0p[g];
                int base = (g * 3 + e_rpo) * 128 + e_sidx;
#pragma unroll
                for (int w2 = 0; w2 < 12; w2++) s += sRedP[w2 * 12 * 128 + base];
                gv[g] = s;
            }
            float nc = sigap(gv[1]) * c0r + sigap(gv[0]) * tanhap(gv[2]);
            c0r = nc;
            __stcg(h0w + hrow * B + BOFF + e_bl, sigap(gv[3]) * tanhap(nc));
        }
        gsync(++epoch);

        {
            ull acc[12][2];
#pragma unroll
            for (int r = 0; r < 12; r++) { acc[r][0] = 0ull; acc[r][1] = 0ull; }
            const float* src   = (w < 6) ? h0w : h1r;
            const int    fbase = (w < 6) ? w * 64 : (w - 6) * 64;
            const int    k0    = w * 64;
            float2 buf[3][4];
#pragma unroll
            for (int gq = 0; gq < 3; gq++)
#pragma unroll
                for (int j = 0; j < 4; j++)
                    buf[gq][j] = __ldcg((const float2*)(src + (fbase + gq * 4 + j) * B + BOFF) + lane);
#pragma unroll
            for (int gq = 0; gq < 16; gq++) {
                const int cur = gq % 3;
                float2 cb[4];
#pragma unroll
                for (int j = 0; j < 4; j++) cb[j] = buf[cur][j];
                if (gq + 3 < 16) {
#pragma unroll
                    for (int j = 0; j < 4; j++)
                        buf[cur][j] = __ldcg((const float2*)(src + (fbase + (gq + 3) * 4 + j) * B + BOFF) + lane);
                }
#pragma unroll
                for (int j = 0; j < 4; j++) {
                    ull hd0 = pack2(cb[j].x, cb[j].x);
                    ull hd1 = pack2(cb[j].y, cb[j].y);
                    const ulonglong2* wb = (const ulonglong2*)(sW1p + (k0 + gq * 4 + j) * 12);
#pragma unroll
                    for (int q = 0; q < 6; q++) {
                        ulonglong2 ww = wb[q];
                        acc[2 * q][0]     = ffma2(hd0, ww.x, acc[2 * q][0]);
                        acc[2 * q][1]     = ffma2(hd1, ww.x, acc[2 * q][1]);
                        acc[2 * q + 1][0] = ffma2(hd0, ww.y, acc[2 * q + 1][0]);
                        acc[2 * q + 1][1] = ffma2(hd1, ww.y, acc[2 * q + 1][1]);
                    }
                }
            }
#pragma unroll
            for (int r = 0; r < 12; r++) {
                ulonglong2 v; v.x = acc[r][0]; v.y = acc[r][1];
                *(ulonglong2*)(sRedP + (w * 12 + r) * 128 + 4 * lane) = v;
            }
        }
        __syncthreads();
        {
            float gv[4];
#pragma unroll
            for (int g = 0; g < 4; g++) {
                float s = 0.0f;
                int base = (g * 3 + e_rpo) * 128 + e_sidx;
#pragma unroll
                for (int w2 = 0; w2 < 12; w2++) s += sRedP[w2 * 12 * 128 + base];
                gv[g] = s;
            }
            float nc = sigap(gv[1]) * c1r + sigap(gv[0]) * tanhap(gv[2]);
            c1r = nc;
            __stcg(h1w + hrow * B + BOFF + e_bl, sigap(gv[3]) * tanhap(nc));
        }
        __syncthreads();
        p ^= 1;
    }

    gsync(++epoch);

    float* s_hb = sRedP;
    float* s_hv = sRedP + 512;
    const float* h1f = g_h1[p];
    const int b = bx;
    s_hb[tid] = __ldcg(h1f + tid * B + b);   // tid < 384 == H
    __syncthreads();
    if (tid < ZH) {
        float a = bias1[tid];
        const float* wr = W1 + tid * H;
#pragma unroll 4
        for (int k = 0; k < H; k++) a = fmaf(s_hb[k], __ldg(wr + k), a);
        s_hv[tid] = fmaxf(a, 0.0f);
    }
    __syncthreads();
    if (tid < Z) {
        float mu = bmu[tid], lv = blv[tid];
        const float* wmu = Wmu + tid * ZH;
        const float* wlv = Wlv + tid * ZH;
#pragma unroll 4
        for (int k = 0; k < ZH; k++) {
            float hk = s_hv[k];
            mu = fmaf(hk, __ldg(wmu + k), mu);
            lv = fmaf(hk, __ldg(wlv + k), lv);
        }
        float zz = mu + eps[b * Z + tid] * expf(0.5f * lv);
        out[b * Z + tid] = mu;
        out[B * Z + b * Z + tid] = lv;
        out[2 * B * Z + b * (H + Z) + H + tid] = zz;
    }
    out[2 * B * Z + b * (H + Z) + tid] = s_hb[tid];   // tid < 384 == H
}

// ---------------- launch ----------------
extern "C" void kernel_launch(void* const* d_in, const int* in_sizes, int n_in,
                              void* d_out, int out_size) {
    const int*   seq   = (const int*)d_in[0];
    const float* eps   = (const float*)d_in[1];
    const float* embed = (const float*)d_in[2];
    const float* Wih0  = (const float*)d_in[3];
    const float* Whh0  = (const float*)d_in[4];
    const float* Wih1  = (const float*)d_in[5];
    const float* Whh1  = (const float*)d_in[6];
    const float* W1    = (const float*)d_in[7];
    const float* b1    = (const float*)d_in[8];
    const float* Wmu   = (const float*)d_in[9];
    const float* bmu   = (const float*)d_in[10];
    const float* Wlv   = (const float*)d_in[11];
    const float* blv   = (const float*)d_in[12];
    float* out = (float*)d_out;

    static int smem_set = 0;
    const int dyn_rnn = 36864 + 73728 + 73728;   // 184320
    if (!smem_set) {
        cudaFuncSetAttribute(rnn_kernel, cudaFuncAttributeMaxDynamicSharedMemorySize, dyn_rnn);
        cudaFuncSetAttribute(pre_mma_kernel, cudaFuncAttributeMaxDynamicSharedMemorySize, PM_SMEM);
        smem_set = 1;
    }

    __nv_bfloat16 *wh, *wl, *eh, *el;
    cudaGetSymbolAddress((void**)&wh, g_Wh);
    cudaGetSymbolAddress((void**)&wl, g_Wl);
    cudaGetSymbolAddress((void**)&eh, g_Eh);
    cudaGetSymbolAddress((void**)&el, g_El);

    act_kernel<<<NSTEP, 128>>>(seq);
    cvt_kernel<<<(FH * E / 4 + 255) / 256, 256>>>(Wih0, wh, wl, FH * E / 4);
    cvt_kernel<<<(VE * E / 4 + 255) / 256, 256>>>(embed, eh, el, VE * E / 4);
    pre_mma_kernel<<<dim3(12, 127), 256, PM_SMEM>>>(seq);
    rnn_kernel<<<128, 384, dyn_rnn>>>(Whh0, Wih1, Whh1, eps, W1, b1, Wmu, bmu, Wlv, blv, out);
}